// round 1
// baseline (speedup 1.0000x reference)
#include <cuda_runtime.h>
#include <cstdint>
#include <math.h>

// Problem constants (fixed shapes from reference)
#define MTOK 2048
#define KDIM 2048
#define NDIM 1408
#define NEXP 8
#define TOPKV 2
#define CAP 1024
#define RROWS (MTOK*TOPKV)   // 4096
#define ECAP (NEXP*CAP)      // 8192

// GEMM tiling
#define BM 128
#define BN 128
#define BKT 16
#define SPAD 20              // 16 + 4 pad -> conflict-free mma fragment LDS
#define NTHR 256

// Scratch (device globals: allocation-free rule)
__device__ __align__(16) float g_gbuf[(size_t)ECAP * NDIM]; // gate pre-act, then SwiGLU act (tf32-rounded)
__device__ __align__(16) float g_ubuf[(size_t)ECAP * NDIM]; // up pre-act
__device__ __align__(16) float g_dbuf[(size_t)ECAP * KDIM]; // down output per routed slot
__device__ int   g_cnt[NEXP];
__device__ int   g_rowtok[ECAP];
__device__ int   g_posmap[RROWS];

__device__ __forceinline__ float to_tf32(float x) {
    float r;
    asm("cvt.rna.tf32.f32 %0, %1;" : "=f"(r) : "f"(x));
    return r;
}

__device__ __forceinline__ float4 cvt4(float4 v) {
    v.x = to_tf32(v.x); v.y = to_tf32(v.y);
    v.z = to_tf32(v.z); v.w = to_tf32(v.w);
    return v;
}

__device__ __forceinline__ void mma8(float4& d, const uint32_t* a, const uint32_t* b) {
    asm volatile(
        "mma.sync.aligned.m16n8k8.row.col.f32.tf32.tf32.f32 "
        "{%0,%1,%2,%3}, {%4,%5,%6,%7}, {%8,%9}, {%0,%1,%2,%3};\n"
        : "+f"(d.x), "+f"(d.y), "+f"(d.z), "+f"(d.w)
        : "r"(a[0]), "r"(a[1]), "r"(a[2]), "r"(a[3]), "r"(b[0]), "r"(b[1]));
}

// ---------------------------------------------------------------------------
// Routing: assign each routed row (token t, slot s) a position within its
// expert group. Slot order differs from the reference's stable sort, but the
// output is invariant to any within-expert permutation.
// ---------------------------------------------------------------------------
__global__ void k_route(const int* __restrict__ idx) {
    __shared__ int sc[NEXP];
    const int tid = threadIdx.x;
    if (tid < NEXP) sc[tid] = 0;
    __syncthreads();
    for (int r = tid; r < RROWS; r += blockDim.x) {
        int e = idx[r];
        int slot = atomicAdd(&sc[e], 1);
        if (slot < CAP) {
            int p = e * CAP + slot;
            g_rowtok[p] = r >> 1;      // TOPK = 2
            g_posmap[r] = p;
        } else {
            g_posmap[r] = e * CAP;     // safety; uniform routing never overflows
        }
    }
    __syncthreads();
    if (tid < NEXP) g_cnt[tid] = min(sc[tid], CAP);
}

// ---------------------------------------------------------------------------
// Grouped NT GEMM: C[r][n] = sum_k A[r][k] * B[n][k], per expert (blockIdx.z).
// A rows beyond the expert's count are zero-filled; tf32 rounding (cvt.rna)
// applied on the smem-store path for both operands. Double-buffered smem with
// register staging (needed because we must cvt, so no cp.async).
//   GATHER: A row r comes from flat_h[rowtok[e*CAP+r]]  (GEMM1 gate/up)
//   else:   A row r comes from g_gbuf[(e*CAP+r)*LDA]    (GEMM2 down)
//   OUTSEL: 0 -> g_gbuf, 1 -> g_ubuf, 2 -> g_dbuf
// ---------------------------------------------------------------------------
template<int LDA, int LDB, int LDC, int KD, bool GATHER, int OUTSEL>
__global__ __launch_bounds__(NTHR, 2)
void k_gemm(const float* __restrict__ Ain, const float* __restrict__ B) {
    const int e    = blockIdx.z;
    const int cnt  = g_cnt[e];
    const int row0 = blockIdx.y * BM;
    if (row0 >= cnt) return;
    const int col0 = blockIdx.x * BN;

    __shared__ __align__(16) float As[2][BM * SPAD];
    __shared__ __align__(16) float Bs[2][BM * SPAD];

    const int tid  = threadIdx.x;
    const int lane = tid & 31;
    const int warp = tid >> 5;
    const int wm   = warp >> 2;      // 2 warps along M
    const int wn   = warp & 3;       // 4 warps along N
    const int grp  = lane >> 2;
    const int tig  = lane & 3;

    // Loader mapping: each thread stages 2 float4 quads for A and 2 for B.
    const int ar0 = tid >> 2;            // rows 0..63
    const int ak0 = (tid & 3) * 4;
    const int ar1 = ar0 + 64;            // rows 64..127
    const int ak1 = ak0;

    const float* Abase = GATHER ? Ain : (const float*)g_gbuf;
    const size_t eB = (size_t)e * ((size_t)NDIM * KDIM);  // same product for all weights

    const bool av0 = (row0 + ar0) < cnt;
    const bool av1 = (row0 + ar1) < cnt;
    const float* ap0;
    const float* ap1;
    if (GATHER) {
        int t0 = av0 ? g_rowtok[e * CAP + row0 + ar0] : 0;
        int t1 = av1 ? g_rowtok[e * CAP + row0 + ar1] : 0;
        ap0 = Abase + (size_t)t0 * LDA + ak0;
        ap1 = Abase + (size_t)t1 * LDA + ak1;
    } else {
        const size_t eA = (size_t)e * CAP * LDA;
        ap0 = Abase + eA + (size_t)(row0 + ar0) * LDA + ak0;
        ap1 = Abase + eA + (size_t)(row0 + ar1) * LDA + ak1;
    }
    const float* bp0 = B + eB + (size_t)(col0 + ar0) * LDB + ak0;
    const float* bp1 = B + eB + (size_t)(col0 + ar1) * LDB + ak1;

    float4 acc[4][4];
#pragma unroll
    for (int i = 0; i < 4; ++i)
#pragma unroll
        for (int j = 0; j < 4; ++j) acc[i][j] = make_float4(0.f, 0.f, 0.f, 0.f);

    // Prologue: stage 0
    {
        float4 pa0 = make_float4(0.f, 0.f, 0.f, 0.f), pa1 = pa0;
        if (av0) pa0 = *(const float4*)ap0;
        if (av1) pa1 = *(const float4*)ap1;
        float4 pb0 = *(const float4*)bp0;
        float4 pb1 = *(const float4*)bp1;
        *(float4*)&As[0][ar0 * SPAD + ak0] = cvt4(pa0);
        *(float4*)&As[0][ar1 * SPAD + ak1] = cvt4(pa1);
        *(float4*)&Bs[0][ar0 * SPAD + ak0] = cvt4(pb0);
        *(float4*)&Bs[0][ar1 * SPAD + ak1] = cvt4(pb1);
    }
    __syncthreads();

    const int KT = KD / BKT;
    int buf = 0;
#pragma unroll 1
    for (int kt = 0; kt < KT; ++kt) {
        float4 na0, na1, nb0v, nb1v;
        const bool more = (kt + 1) < KT;
        if (more) {
            const int ko = (kt + 1) * BKT;
            na0 = make_float4(0.f, 0.f, 0.f, 0.f); na1 = na0;
            if (av0) na0 = *(const float4*)(ap0 + ko);
            if (av1) na1 = *(const float4*)(ap1 + ko);
            nb0v = *(const float4*)(bp0 + ko);
            nb1v = *(const float4*)(bp1 + ko);
        }

        // Compute current stage: 2 x k8 steps, 32 mma
#pragma unroll
        for (int ks = 0; ks < BKT; ks += 8) {
            uint32_t af[4][4], bf[4][2];
#pragma unroll
            for (int mt = 0; mt < 4; ++mt) {
                const int rb = wm * 64 + mt * 16;
                const float* s = &As[buf][0];
                af[mt][0] = __float_as_uint(s[(rb + grp    ) * SPAD + ks + tig    ]);
                af[mt][1] = __float_as_uint(s[(rb + grp + 8) * SPAD + ks + tig    ]);
                af[mt][2] = __float_as_uint(s[(rb + grp    ) * SPAD + ks + tig + 4]);
                af[mt][3] = __float_as_uint(s[(rb + grp + 8) * SPAD + ks + tig + 4]);
            }
#pragma unroll
            for (int nt = 0; nt < 4; ++nt) {
                const int cb = wn * 32 + nt * 8;
                const float* s = &Bs[buf][0];
                bf[nt][0] = __float_as_uint(s[(cb + grp) * SPAD + ks + tig    ]);
                bf[nt][1] = __float_as_uint(s[(cb + grp) * SPAD + ks + tig + 4]);
            }
#pragma unroll
            for (int mt = 0; mt < 4; ++mt)
#pragma unroll
                for (int nt = 0; nt < 4; ++nt)
                    mma8(acc[mt][nt], af[mt], bf[nt]);
        }

        if (more) {
            const int nb = buf ^ 1;
            *(float4*)&As[nb][ar0 * SPAD + ak0] = cvt4(na0);
            *(float4*)&As[nb][ar1 * SPAD + ak1] = cvt4(na1);
            *(float4*)&Bs[nb][ar0 * SPAD + ak0] = cvt4(nb0v);
            *(float4*)&Bs[nb][ar1 * SPAD + ak1] = cvt4(nb1v);
        }
        __syncthreads();
        buf ^= 1;
    }

    // Epilogue
    float* Cbase;
    if (OUTSEL == 0)      Cbase = g_gbuf;
    else if (OUTSEL == 1) Cbase = g_ubuf;
    else                  Cbase = g_dbuf;
    const size_t eC = (size_t)e * CAP;
#pragma unroll
    for (int mt = 0; mt < 4; ++mt) {
        const int r0 = row0 + wm * 64 + mt * 16 + grp;
        const int r1 = r0 + 8;
#pragma unroll
        for (int nt = 0; nt < 4; ++nt) {
            const int c = col0 + wn * 32 + nt * 8 + tig * 2;
            float4 v = acc[mt][nt];
            if (r0 < cnt) *(float2*)&Cbase[(eC + r0) * LDC + c] = make_float2(v.x, v.y);
            if (r1 < cnt) *(float2*)&Cbase[(eC + r1) * LDC + c] = make_float2(v.z, v.w);
        }
    }
}

// ---------------------------------------------------------------------------
// SwiGLU activation: act = silu(min(g,10)) * clip(u,-10,10), in place over
// g_gbuf, tf32-rounded for GEMM2 consumption.
// ---------------------------------------------------------------------------
__device__ __forceinline__ float actf(float g, float u) {
    g = fminf(g, 10.0f);
    u = fminf(fmaxf(u, -10.0f), 10.0f);
    float s = g / (1.0f + expf(-g));
    return to_tf32(s * u);
}

__global__ void k_act() {
    const int slot = blockIdx.x;
    const int e = slot / CAP;
    const int p = slot % CAP;
    if (p >= g_cnt[e]) return;
    const size_t off = (size_t)slot * NDIM;
    float4* g4 = (float4*)(g_gbuf + off);
    const float4* u4 = (const float4*)(g_ubuf + off);
    for (int i = threadIdx.x; i < NDIM / 4; i += blockDim.x) {
        float4 gv = g4[i];
        float4 uv = u4[i];
        float4 r;
        r.x = actf(gv.x, uv.x);
        r.y = actf(gv.y, uv.y);
        r.z = actf(gv.z, uv.z);
        r.w = actf(gv.w, uv.w);
        g4[i] = r;
    }
}

// ---------------------------------------------------------------------------
// Combine: out[t] = gate0 * d[pos0] + gate1 * d[pos1]. Pure gather, no
// atomics, deterministic.
// ---------------------------------------------------------------------------
__global__ void k_combine(const float* __restrict__ gate, float* __restrict__ out) {
    const int t = blockIdx.x;
    const int p0 = g_posmap[2 * t];
    const int p1 = g_posmap[2 * t + 1];
    const float g0 = gate[2 * t];
    const float g1 = gate[2 * t + 1];
    const float4* d0 = (const float4*)(g_dbuf + (size_t)p0 * KDIM);
    const float4* d1 = (const float4*)(g_dbuf + (size_t)p1 * KDIM);
    float4* o = (float4*)(out + (size_t)t * KDIM);
    for (int i = threadIdx.x; i < KDIM / 4; i += blockDim.x) {
        float4 a = d0[i];
        float4 b = d1[i];
        o[i] = make_float4(g0 * a.x + g1 * b.x, g0 * a.y + g1 * b.y,
                           g0 * a.z + g1 * b.z, g0 * a.w + g1 * b.w);
    }
}

extern "C" void kernel_launch(void* const* d_in, const int* in_sizes, int n_in,
                              void* d_out, int out_size) {
    (void)in_sizes; (void)n_in; (void)out_size;
    const float* flat_h    = (const float*)d_in[0];
    const int*   flat_idx  = (const int*)  d_in[1];
    const float* flat_gate = (const float*)d_in[2];
    const float* gate_w    = (const float*)d_in[3];
    const float* up_w      = (const float*)d_in[4];
    const float* down_w    = (const float*)d_in[5];
    float* out = (float*)d_out;

    k_route<<<1, 256>>>(flat_idx);

    dim3 grid1(NDIM / BN, CAP / BM, NEXP);   // (11, 8, 8)
    k_gemm<KDIM, KDIM, NDIM, KDIM, true, 0><<<grid1, NTHR>>>(flat_h, gate_w);
    k_gemm<KDIM, KDIM, NDIM, KDIM, true, 1><<<grid1, NTHR>>>(flat_h, up_w);

    k_act<<<ECAP, 256>>>();

    dim3 grid2(KDIM / BN, CAP / BM, NEXP);   // (16, 8, 8)
    k_gemm<NDIM, NDIM, KDIM, NDIM, false, 2><<<grid2, NTHR>>>(nullptr, down_w);

    k_combine<<<MTOK, 256>>>(flat_gate, out);
}